// round 6
// baseline (speedup 1.0000x reference)
#include <cuda_runtime.h>

// x[64, 64, 64, 128] fp32.
//   out1 = FWHT along axis 1 (i, len 64)  : element stride 8192 floats
//   out2 = FWHT along axis 2 (j, len 64) of out1 : element stride 128 floats
// d_out = [out1 | out2].
//
// Two streaming kernels; each thread owns TWO adjacent channels (one float2
// column) along the transform axis -> 64 LDG.64 + 64 STG.64 per thread.
// This halves LSU issue pressure vs the scalar version (which was co-binding
// with DRAM at 71%), leaving DRAM as the only limiter.
// All warp accesses are 256B contiguous. Butterfly is register-resident.

#define THREADS 128
#define NCOLS2 (64u * 64u * 64u * 128u / 64u / 2u)   // 2^18 float2 columns
#define GRID   (NCOLS2 / THREADS)                    // 2048

template <int S2, bool REVERSE>   // S2 = stride in float2 units
__global__ __launch_bounds__(THREADS)
void fwht_axis_kernel(const float2* __restrict__ in, float2* __restrict__ out)
{
    const unsigned blk = REVERSE ? (GRID - 1u - blockIdx.x) : blockIdx.x;
    const unsigned g   = blk * THREADS + threadIdx.x;      // 0 .. 2^18-1
    const size_t base  = (size_t)(g / S2) * (64u * S2) + (g % S2);

    float2 v[64];
#pragma unroll
    for (int k = 0; k < 64; k++) {
        const float4* p = reinterpret_cast<const float4*>(in + base + (size_t)k * S2);
        // __ldcs on float2 via components to keep the 8B vector load:
        v[k] = __ldcs(in + base + (size_t)k * S2);
        (void)p;
    }

#pragma unroll
    for (int h = 1; h < 64; h <<= 1) {
#pragma unroll
        for (int s = 0; s < 64; s += 2 * h) {
#pragma unroll
            for (int k = 0; k < h; k++) {
                float2 a = v[s + k];
                float2 b = v[s + k + h];
                v[s + k].x     = a.x + b.x;
                v[s + k].y     = a.y + b.y;
                v[s + k + h].x = a.x - b.x;
                v[s + k + h].y = a.y - b.y;
            }
        }
    }

    if (REVERSE) {
#pragma unroll
        for (int k = 0; k < 64; k++)
            __stcs(out + base + (size_t)k * S2, v[k]);
    } else {
#pragma unroll
        for (int k = 0; k < 64; k++)
            out[base + (size_t)k * S2] = v[k];
    }
}

extern "C" void kernel_launch(void* const* d_in, const int* in_sizes, int n_in,
                              void* d_out, int out_size)
{
    const float2* x = (const float2*)d_in[0];
    float2* out1 = (float2*)d_out;
    float2* out2 = out1 + (size_t)64 * 64 * 64 * 128 / 2;

    // axis 1: stride 8192 floats = 4096 float2
    fwht_axis_kernel<4096, false><<<GRID, THREADS>>>(x, out1);
    // axis 2: stride 128 floats = 64 float2, reverse order
    fwht_axis_kernel<64, true><<<GRID, THREADS>>>(out1, out2);
}